// round 3
// baseline (speedup 1.0000x reference)
#include <cuda_runtime.h>
#include <cstdint>

// Problem constants
#define T_SEQ 200
#define BATCH 1024
#define EMB   128
#define HID   128
#define G3    384          // 3*HID, gate order r,z,n
#define NROWS (BATCH * T_SEQ)

// 314 MB scratch for gx = x @ W_ih^T + b_ih  (static __device__: allocation-free)
__device__ float g_gx[(size_t)NROWS * G3];

// Packed fp32x2 FMA: d.lo += a.lo*b.lo ; d.hi += a.hi*b.hi
__device__ __forceinline__ void fma2(unsigned long long& d,
                                     unsigned long long a,
                                     unsigned long long b) {
    asm("fma.rn.f32x2 %0, %1, %2, %0;" : "+l"(d) : "l"(a), "l"(b));
}
__device__ __forceinline__ float pairsum(unsigned long long d) {
    float lo = __uint_as_float((unsigned)(d & 0xffffffffULL));
    float hi = __uint_as_float((unsigned)(d >> 32));
    return lo + hi;
}

// ---------------------------------------------------------------------------
// Kernel 1: fused embedding gather + input-side GEMM (unchanged from R2)
// ---------------------------------------------------------------------------
#define RM    64
#define XPAD  132          // 33 float4s per row: odd pitch -> conflict-free
#define SM1_BYTES ((RM * XPAD + 128 * XPAD) * 4)

__global__ __launch_bounds__(256) void gx_kernel(
    const int*   __restrict__ seq,
    const float* __restrict__ emb,
    const float* __restrict__ Wih,
    const float* __restrict__ bih)
{
    extern __shared__ float sm[];
    float* xs = sm;                  // [RM][XPAD]   x tile, k-major
    float* ws = sm + RM * XPAD;      // [128][XPAD]  W tile, k-major

    const int t    = threadIdx.x;
    const int row0 = blockIdx.x * RM;
    const int c0   = blockIdx.y * 128;

    {
        int r  = t >> 2;
        int k0 = (t & 3) * 32;
        int idx = __ldg(seq + row0 + r);
        const float4* src = (const float4*)(emb + (size_t)idx * EMB + k0);
        float4* dst = (float4*)(xs + r * XPAD + k0);
        #pragma unroll
        for (int i = 0; i < 8; i++) dst[i] = src[i];
    }
    {
        #pragma unroll
        for (int i = 0; i < 16; i++) {
            int flat = t + 256 * i;
            int c  = flat >> 5;
            int k4 = (flat & 31) << 2;
            *(float4*)(ws + c * XPAD + k4) =
                *(const float4*)(Wih + (size_t)(c0 + c) * EMB + k4);
        }
    }
    __syncthreads();

    const int rg = t >> 5;
    const int cg = t & 31;
    unsigned long long acc[8][4];
    #pragma unroll
    for (int r = 0; r < 8; r++)
        #pragma unroll
        for (int j = 0; j < 4; j++) acc[r][j] = 0ULL;

    const float* xbase = xs + (rg * 8) * XPAD;

    #pragma unroll 4
    for (int k = 0; k < 128; k += 4) {
        ulonglong2 wv[4];
        #pragma unroll
        for (int j = 0; j < 4; j++)
            wv[j] = *(const ulonglong2*)(ws + (cg + 32 * j) * XPAD + k);
        #pragma unroll
        for (int r = 0; r < 8; r++) {
            ulonglong2 xv = *(const ulonglong2*)(xbase + r * XPAD + k);
            #pragma unroll
            for (int j = 0; j < 4; j++) {
                fma2(acc[r][j], xv.x, wv[j].x);
                fma2(acc[r][j], xv.y, wv[j].y);
            }
        }
    }

    #pragma unroll
    for (int j = 0; j < 4; j++) {
        int c = c0 + cg + 32 * j;
        float bv = __ldg(bih + c);
        #pragma unroll
        for (int r = 0; r < 8; r++) {
            int row = row0 + rg * 8 + r;
            g_gx[(size_t)row * G3 + c] = pairsum(acc[r][j]) + bv;
        }
    }
}

// ---------------------------------------------------------------------------
// Kernel 2: GRU recurrence, minimal-LDS mapping.
// 384 threads/CTA; thread t owns gate g=t across all 8 batch rows.
// Per 4-k chunk: 1 private W LDS.128 (conflict-free, loaded ONCE per CTA-step)
// + 8 broadcast h LDS.128 (free) + 16 fma2 into 8 register accumulators.
// LDS traffic per CTA-step: ~200 KB vs 917 KB before.
// ---------------------------------------------------------------------------
#define BM     8
#define NTHR   384
#define KPAD   132
#define GHPAD  388
#define SM2_BYTES ((G3 * KPAD + BM * KPAD + BM * GHPAD + G3) * 4)

__device__ __forceinline__ float fsigmoid(float x) {
    return __fdividef(1.f, 1.f + __expf(-x));
}

__global__ __launch_bounds__(NTHR) void gru_kernel(
    const float* __restrict__ Whh,
    const float* __restrict__ bhh,
    float*       __restrict__ out)
{
    extern __shared__ float sm[];
    float* ws  = sm;                          // [G3][KPAD]  W_hh, k-contiguous
    float* hs  = ws + G3 * KPAD;              // [BM][KPAD]  hidden state
    float* ghs = hs + BM * KPAD;              // [BM][GHPAD] gh scratch
    float* bhs = ghs + BM * GHPAD;            // [G3]        b_hh

    const int t  = threadIdx.x;
    const int b0 = blockIdx.x * BM;

    // ---- load W_hh into SMEM (12288 float4s, 32 per thread) ----
    #pragma unroll
    for (int i = 0; i < 32; i++) {
        int flat = t + NTHR * i;
        int g  = flat >> 5;
        int k4 = (flat & 31) << 2;
        *(float4*)(ws + g * KPAD + k4) = *(const float4*)(Whh + (size_t)g * HID + k4);
    }
    bhs[t] = bhh[t];
    // ---- h = 0 ----
    for (int pos = t; pos < BM * 128; pos += NTHR)
        hs[(pos >> 7) * KPAD + (pos & 127)] = 0.f;
    __syncthreads();

    // phase-1: this thread's gate
    const float* wp = ws + t * KPAD;
    const unsigned long long binit = (unsigned long long)__float_as_uint(bhs[t]);

    // phase-2 mapping: up to 3 (row,k) positions per thread (1024 = 384*2 + 256)
    int pr[3], pk[3];
    bool pv[3];
    #pragma unroll
    for (int p = 0; p < 3; p++) {
        int pos = t + NTHR * p;
        pv[p] = (pos < BM * 128);
        pr[p] = (pos >> 7) & 7;
        pk[p] = pos & 127;
    }

    for (int ts = 0; ts < T_SEQ; ts++) {
        // ---- prefetch this step's gx (hidden under the GEMM) ----
        float xr[3], xz[3], xn[3];
        #pragma unroll
        for (int p = 0; p < 3; p++) {
            if (pv[p]) {
                const float* gp = g_gx + ((size_t)(b0 + pr[p]) * T_SEQ + ts) * G3 + pk[p];
                xr[p] = __ldg(gp);
                xz[p] = __ldg(gp + 128);
                xn[p] = __ldg(gp + 256);
            }
        }

        // ---- phase 1: gh[g, r] for all 8 rows, W loaded once ----
        unsigned long long a[BM];
        #pragma unroll
        for (int r = 0; r < BM; r++) a[r] = binit;   // lo=bias, hi=0

        #pragma unroll 8
        for (int k = 0; k < 128; k += 4) {
            ulonglong2 wv = *(const ulonglong2*)(wp + k);
            #pragma unroll
            for (int r = 0; r < BM; r++) {
                ulonglong2 hv = *(const ulonglong2*)(hs + r * KPAD + k);
                fma2(a[r], hv.x, wv.x);
                fma2(a[r], hv.y, wv.y);
            }
        }
        #pragma unroll
        for (int r = 0; r < BM; r++)
            ghs[r * GHPAD + t] = pairsum(a[r]);
        __syncthreads();

        // ---- phase 2: gates + hidden update ----
        #pragma unroll
        for (int p = 0; p < 3; p++) {
            if (pv[p]) {
                int r = pr[p], k = pk[p];
                float hrv = ghs[r * GHPAD + k];
                float hzv = ghs[r * GHPAD + 128 + k];
                float hnv = ghs[r * GHPAD + 256 + k];
                float hprev = hs[r * KPAD + k];
                float rr = fsigmoid(xr[p] + hrv);
                float zz = fsigmoid(xz[p] + hzv);
                float narg = xn[p] + rr * hnv;
                float nn = 2.f * fsigmoid(2.f * narg) - 1.f;   // tanh
                hs[r * KPAD + k] = (1.f - zz) * nn + zz * hprev;
            }
        }
        __syncthreads();
    }

    // ---- write final hidden state ----
    #pragma unroll
    for (int p = 0; p < 3; p++) {
        if (pv[p])
            out[(size_t)(b0 + pr[p]) * HID + pk[p]] = hs[pr[p] * KPAD + pk[p]];
    }
}

// ---------------------------------------------------------------------------
// Launch
// ---------------------------------------------------------------------------
extern "C" void kernel_launch(void* const* d_in, const int* in_sizes, int n_in,
                              void* d_out, int out_size)
{
    const int*   seq = (const int*)  d_in[0];  // [1024, 200] int32
    const float* emb = (const float*)d_in[1];  // [100000, 128]
    const float* Wih = (const float*)d_in[2];  // [384, 128]
    const float* Whh = (const float*)d_in[3];  // [384, 128]
    const float* bih = (const float*)d_in[4];  // [384]
    const float* bhh = (const float*)d_in[5];  // [384]
    float* out = (float*)d_out;                // [1024, 128]

    cudaFuncSetAttribute(gx_kernel,  cudaFuncAttributeMaxDynamicSharedMemorySize, SM1_BYTES);
    cudaFuncSetAttribute(gru_kernel, cudaFuncAttributeMaxDynamicSharedMemorySize, SM2_BYTES);

    dim3 grid1(NROWS / RM, G3 / 128);          // 3200 x 3
    gx_kernel<<<grid1, 256, SM1_BYTES>>>(seq, emb, Wih, bih);

    gru_kernel<<<BATCH / BM, NTHR, SM2_BYTES>>>(Whh, bhh, out);
}

// round 4
// speedup vs baseline: 1.1066x; 1.1066x over previous
#include <cuda_runtime.h>
#include <cstdint>

// Problem constants
#define T_SEQ 200
#define BATCH 1024
#define EMB   128
#define HID   128
#define G3    384          // 3*HID, gate order r,z,n
#define NROWS (BATCH * T_SEQ)

// 314 MB scratch for gx = x @ W_ih^T + b_ih  (static __device__: allocation-free)
__device__ float g_gx[(size_t)NROWS * G3];

// Packed fp32x2 FMA (used by gru kernel)
__device__ __forceinline__ void fma2(unsigned long long& d,
                                     unsigned long long a,
                                     unsigned long long b) {
    asm("fma.rn.f32x2 %0, %1, %2, %0;" : "+l"(d) : "l"(a), "l"(b));
}
__device__ __forceinline__ float pairsum(unsigned long long d) {
    float lo = __uint_as_float((unsigned)(d & 0xffffffffULL));
    float hi = __uint_as_float((unsigned)(d >> 32));
    return lo + hi;
}

// tf32 helpers
__device__ __forceinline__ unsigned to_tf32(float x) {
    unsigned r;
    asm("cvt.rna.tf32.f32 %0, %1;" : "=r"(r) : "f"(x));
    return r;
}
__device__ __forceinline__ void split_tf32(float x, unsigned& hi, unsigned& lo) {
    hi = to_tf32(x);
    lo = to_tf32(x - __uint_as_float(hi));
}
// D += A*B  (m16n8k8 tf32, fp32 accum)
__device__ __forceinline__ void mma_tf32(float* c,
                                         unsigned a0, unsigned a1, unsigned a2, unsigned a3,
                                         unsigned b0, unsigned b1) {
    asm("mma.sync.aligned.m16n8k8.row.col.f32.tf32.tf32.f32 "
        "{%0,%1,%2,%3}, {%4,%5,%6,%7}, {%8,%9}, {%0,%1,%2,%3};"
        : "+f"(c[0]), "+f"(c[1]), "+f"(c[2]), "+f"(c[3])
        : "r"(a0), "r"(a1), "r"(a2), "r"(a3), "r"(b0), "r"(b1));
}

// ---------------------------------------------------------------------------
// Kernel 1: fused embedding gather + input GEMM on tensor cores.
//   gx[row, c] = sum_k emb[seq[row], k] * W_ih[c, k] + b_ih[c]
// CTA tile 128 rows x 128 cols x K=128. 8 warps, warp tile 32(M) x 64(N).
// fp32 x and W staged in SMEM (pitch 132 -> conflict-free fragment loads);
// operands split hi/lo tf32 in registers; 3-pass accumulation
// (hi*hi + hi*lo + lo*hi) gives fp32-equivalent precision.
// ---------------------------------------------------------------------------
#define MTILE 128
#define KPAD1 132
#define SM1_BYTES ((MTILE * KPAD1 + 128 * KPAD1) * 4)

__global__ __launch_bounds__(256) void gx_kernel(
    const int*   __restrict__ seq,
    const float* __restrict__ emb,
    const float* __restrict__ Wih,
    const float* __restrict__ bih)
{
    extern __shared__ float sm[];
    float* xs = sm;                    // [128][KPAD1]  x tile (k-major)
    float* ws = sm + MTILE * KPAD1;    // [128][KPAD1]  W tile (k-major)

    const int t    = threadIdx.x;
    const int row0 = blockIdx.x * MTILE;
    const int c0   = blockIdx.y * 128;

    // ---- stage x tile (embedding gather): 2 threads per row, 64 floats each
    {
        int r  = t >> 1;
        int k0 = (t & 1) * 64;
        int idx = __ldg(seq + row0 + r);
        const float4* src = (const float4*)(emb + (size_t)idx * EMB + k0);
        float4* dst = (float4*)(xs + r * KPAD1 + k0);
        #pragma unroll
        for (int i = 0; i < 16; i++) dst[i] = src[i];
    }
    // ---- stage W tile
    {
        int c  = t >> 1;
        int k0 = (t & 1) * 64;
        const float4* src = (const float4*)(Wih + (size_t)(c0 + c) * EMB + k0);
        float4* dst = (float4*)(ws + c * KPAD1 + k0);
        #pragma unroll
        for (int i = 0; i < 16; i++) dst[i] = src[i];
    }
    __syncthreads();

    // ---- warp tiling: 4x2 warps; warp tile M=32 (2 m-subtiles), N=64 (8 n-subtiles)
    const int w     = t >> 5;
    const int lane  = t & 31;
    const int mrow0 = (w & 3) * 32;
    const int ncol0 = (w >> 2) * 64;
    const int gid   = lane >> 2;       // 0..7
    const int tig   = lane & 3;        // 0..3

    float acc[2][8][4];
    #pragma unroll
    for (int m = 0; m < 2; m++)
        #pragma unroll
        for (int n = 0; n < 8; n++)
            #pragma unroll
            for (int i = 0; i < 4; i++) acc[m][n][i] = 0.f;

    #pragma unroll 4
    for (int ks = 0; ks < 16; ks++) {
        const int k0 = ks * 8;
        // A fragments for both m-subtiles: split hi/lo
        unsigned ah[2][4], al[2][4];
        #pragma unroll
        for (int m = 0; m < 2; m++) {
            const float* ab = xs + (mrow0 + m * 16 + gid) * KPAD1 + k0 + tig;
            split_tf32(ab[0],            ah[m][0], al[m][0]);
            split_tf32(ab[8 * KPAD1],    ah[m][1], al[m][1]);
            split_tf32(ab[4],            ah[m][2], al[m][2]);
            split_tf32(ab[8 * KPAD1 + 4],ah[m][3], al[m][3]);
        }
        #pragma unroll
        for (int n = 0; n < 8; n++) {
            const float* bb = ws + (ncol0 + n * 8 + gid) * KPAD1 + k0 + tig;
            unsigned bh0, bl0, bh1, bl1;
            split_tf32(bb[0], bh0, bl0);
            split_tf32(bb[4], bh1, bl1);
            #pragma unroll
            for (int m = 0; m < 2; m++) {
                mma_tf32(acc[m][n], ah[m][0], ah[m][1], ah[m][2], ah[m][3], bh0, bh1); // hi*hi
                mma_tf32(acc[m][n], ah[m][0], ah[m][1], ah[m][2], ah[m][3], bl0, bl1); // hi*lo
                mma_tf32(acc[m][n], al[m][0], al[m][1], al[m][2], al[m][3], bh0, bh1); // lo*hi
            }
        }
    }

    // ---- epilogue: + bias, float2 stores to g_gx
    #pragma unroll
    for (int n = 0; n < 8; n++) {
        int col = c0 + ncol0 + n * 8 + 2 * tig;
        float2 bv = *(const float2*)(bih + col);
        #pragma unroll
        for (int m = 0; m < 2; m++) {
            int r0 = row0 + mrow0 + m * 16 + gid;
            float2 v0 = { acc[m][n][0] + bv.x, acc[m][n][1] + bv.y };
            float2 v1 = { acc[m][n][2] + bv.x, acc[m][n][3] + bv.y };
            *(float2*)(g_gx + (size_t)r0 * G3 + col)       = v0;
            *(float2*)(g_gx + (size_t)(r0 + 8) * G3 + col) = v1;
        }
    }
}

// ---------------------------------------------------------------------------
// Kernel 2: GRU recurrence (R2 version, verbatim — best known: 739 us).
// ---------------------------------------------------------------------------
#define BM     8
#define KPAD   132
#define GHPAD  388
#define SM2_BYTES ((G3 * KPAD + BM * KPAD + BM * GHPAD + G3) * 4)

__device__ __forceinline__ float fsigmoid(float x) {
    return __fdividef(1.f, 1.f + __expf(-x));
}

__global__ __launch_bounds__(256) void gru_kernel(
    const float* __restrict__ Whh,
    const float* __restrict__ bhh,
    float*       __restrict__ out)
{
    extern __shared__ float sm[];
    float* ws  = sm;                          // [G3][KPAD]  W_hh, k-contiguous
    float* hs  = ws + G3 * KPAD;              // [BM][KPAD]  hidden state
    float* ghs = hs + BM * KPAD;              // [BM][GHPAD] gh scratch
    float* bhs = ghs + BM * GHPAD;            // [G3]        b_hh

    const int t  = threadIdx.x;
    const int b0 = blockIdx.x * BM;

    #pragma unroll
    for (int i = 0; i < 48; i++) {
        int flat = t + 256 * i;               // 12288 float4s = 384 g x 32 k4
        int g  = flat >> 5;
        int k4 = (flat & 31) << 2;
        *(float4*)(ws + g * KPAD + k4) = *(const float4*)(Whh + (size_t)g * HID + k4);
    }
    if (t < 128) {
        bhs[t]       = bhh[t];
        bhs[t + 128] = bhh[t + 128];
        bhs[t + 256] = bhh[t + 256];
    }
    #pragma unroll
    for (int p = 0; p < 4; p++) {
        int pos = t + 256 * p;
        hs[(pos >> 7) * KPAD + (pos & 127)] = 0.f;
    }
    __syncthreads();

    const int gg = t >> 1;                    // 0..127
    const int rg = t & 1;                     // 0..1
    const int g0 = gg * 3;
    const float* wp0 = ws + (g0 + 0) * KPAD;
    const float* wp1 = ws + (g0 + 1) * KPAD;
    const float* wp2 = ws + (g0 + 2) * KPAD;
    const float* hp  = hs + (rg * 4) * KPAD;
    const float bb0 = bhs[g0], bb1 = bhs[g0 + 1], bb2 = bhs[g0 + 2];

    int pr[4], pk[4];
    #pragma unroll
    for (int p = 0; p < 4; p++) { int pos = t + 256 * p; pr[p] = pos >> 7; pk[p] = pos & 127; }

    for (int ts = 0; ts < T_SEQ; ts++) {
        float xr[4], xz[4], xn[4];
        #pragma unroll
        for (int p = 0; p < 4; p++) {
            const float* gp = g_gx + ((size_t)(b0 + pr[p]) * T_SEQ + ts) * G3 + pk[p];
            xr[p] = __ldg(gp);
            xz[p] = __ldg(gp + 128);
            xn[p] = __ldg(gp + 256);
        }

        unsigned long long a0[4], a1[4], a2[4];
        #pragma unroll
        for (int r = 0; r < 4; r++) {
            a0[r] = (unsigned long long)__float_as_uint(bb0);   // lo=bias, hi=0
            a1[r] = (unsigned long long)__float_as_uint(bb1);
            a2[r] = (unsigned long long)__float_as_uint(bb2);
        }

        #pragma unroll 4
        for (int k = 0; k < 128; k += 4) {
            ulonglong2 w0 = *(const ulonglong2*)(wp0 + k);
            ulonglong2 w1 = *(const ulonglong2*)(wp1 + k);
            ulonglong2 w2 = *(const ulonglong2*)(wp2 + k);
            #pragma unroll
            for (int r = 0; r < 4; r++) {
                ulonglong2 hv = *(const ulonglong2*)(hp + r * KPAD + k);
                fma2(a0[r], hv.x, w0.x);  fma2(a0[r], hv.y, w0.y);
                fma2(a1[r], hv.x, w1.x);  fma2(a1[r], hv.y, w1.y);
                fma2(a2[r], hv.x, w2.x);  fma2(a2[r], hv.y, w2.y);
            }
        }
        #pragma unroll
        for (int r = 0; r < 4; r++) {
            int row = rg * 4 + r;
            ghs[row * GHPAD + g0 + 0] = pairsum(a0[r]);
            ghs[row * GHPAD + g0 + 1] = pairsum(a1[r]);
            ghs[row * GHPAD + g0 + 2] = pairsum(a2[r]);
        }
        __syncthreads();

        #pragma unroll
        for (int p = 0; p < 4; p++) {
            int r = pr[p], k = pk[p];
            float hrv = ghs[r * GHPAD + k];
            float hzv = ghs[r * GHPAD + 128 + k];
            float hnv = ghs[r * GHPAD + 256 + k];
            float hprev = hs[r * KPAD + k];
            float rr = fsigmoid(xr[p] + hrv);
            float zz = fsigmoid(xz[p] + hzv);
            float narg = xn[p] + rr * hnv;
            float nn = 2.f * fsigmoid(2.f * narg) - 1.f;   // tanh
            hs[r * KPAD + k] = (1.f - zz) * nn + zz * hprev;
        }
        __syncthreads();
    }

    #pragma unroll
    for (int p = 0; p < 4; p++) {
        out[(size_t)(b0 + pr[p]) * HID + pk[p]] = hs[pr[p] * KPAD + pk[p]];
    }
}

// ---------------------------------------------------------------------------
// Launch
// ---------------------------------------------------------------------------
extern "C" void kernel_launch(void* const* d_in, const int* in_sizes, int n_in,
                              void* d_out, int out_size)
{
    const int*   seq = (const int*)  d_in[0];  // [1024, 200] int32
    const float* emb = (const float*)d_in[1];  // [100000, 128]
    const float* Wih = (const float*)d_in[2];  // [384, 128]
    const float* Whh = (const float*)d_in[3];  // [384, 128]
    const float* bih = (const float*)d_in[4];  // [384]
    const float* bhh = (const float*)d_in[5];  // [384]
    float* out = (float*)d_out;                // [1024, 128]

    cudaFuncSetAttribute(gx_kernel,  cudaFuncAttributeMaxDynamicSharedMemorySize, SM1_BYTES);
    cudaFuncSetAttribute(gru_kernel, cudaFuncAttributeMaxDynamicSharedMemorySize, SM2_BYTES);

    dim3 grid1(NROWS / MTILE, G3 / 128);       // 1600 x 3
    gx_kernel<<<grid1, 256, SM1_BYTES>>>(seq, emb, Wih, bih);

    gru_kernel<<<BATCH / BM, 256, SM2_BYTES>>>(Whh, bhh, out);
}